// round 1
// baseline (speedup 1.0000x reference)
#include <cuda_runtime.h>
#include <cstdint>

// CrossAttention: B=4, H=W=32 (N=1024), C=512, heads=8, hd=64
// q patch = whole image (1024 queries), k/v patches = 4x4 (64 patches x 16 keys)
// out[b,h,p,i,d] : [4,8,64,1024,64] fp32

typedef unsigned long long ull;

#define B_    4
#define NH    8
#define SEQ   1024
#define HD    64
#define CD    512
#define PS    64
#define S2    16
#define SCALE 0.125f

__device__ __align__(16) float g_q[B_*NH*SEQ*HD];      // [b,h,i,d]
__device__ __align__(16) float g_k[B_*NH*PS*S2*HD];    // [b,h,p,j,d]
__device__ __align__(16) float g_v[B_*NH*PS*S2*HD];

__device__ __forceinline__ ull fma2(ull a, ull b, ull c) {
    ull d; asm("fma.rn.f32x2 %0, %1, %2, %3;" : "=l"(d) : "l"(a), "l"(b), "l"(c)); return d;
}
__device__ __forceinline__ ull add2(ull a, ull b) {
    ull d; asm("add.rn.f32x2 %0, %1, %2;" : "=l"(d) : "l"(a), "l"(b)); return d;
}
__device__ __forceinline__ ull pack2(float lo, float hi) {
    ull d; asm("mov.b64 %0, {%1, %2};" : "=l"(d) : "f"(lo), "f"(hi)); return d;
}
__device__ __forceinline__ float2 unpack2(ull v) {
    float2 r; asm("mov.b64 {%0, %1}, %2;" : "=f"(r.x), "=f"(r.y) : "l"(v)); return r;
}

// ---------------------------------------------------------------------------
// Fused QKV projection: y = X @ W + b, M=4096, N=512, K=512, z picks q/k/v.
// 128x128 tile, BK=16, 256 threads, 8x8 per thread, f32x2 inner product.
// Epilogue scatters K/V into patch-grouped layout.
// ---------------------------------------------------------------------------
__global__ void __launch_bounds__(256) proj_kernel(
    const float* __restrict__ x_s, const float* __restrict__ x_l,
    const float* __restrict__ Wq, const float* __restrict__ bq,
    const float* __restrict__ Wk, const float* __restrict__ bk,
    const float* __restrict__ Wv, const float* __restrict__ bv)
{
    const int z = blockIdx.z;
    const float* X  = (z == 0) ? x_l : x_s;
    const float* W  = (z == 0) ? Wq : (z == 1 ? Wk : Wv);
    const float* bs = (z == 0) ? bq : (z == 1 ? bk : bv);
    float* out      = (z == 0) ? g_q : (z == 1 ? g_k : g_v);

    __shared__ __align__(16) float As[16][132];   // [k][m] transposed
    __shared__ __align__(16) float Bs[16][132];   // [k][n]

    const int tid = threadIdx.x;
    const int tx = tid & 15, ty = tid >> 4;
    const int m0 = blockIdx.y * 128;
    const int n0 = blockIdx.x * 128;

    const int arow = tid >> 2, ac4 = (tid & 3) * 4;
    const int brow = tid >> 5, bn4 = (tid & 31) * 4;

    float4 a_st[2], b_st[2];

    ull acc[8][4];
    #pragma unroll
    for (int i = 0; i < 8; i++)
        #pragma unroll
        for (int j = 0; j < 4; j++) acc[i][j] = 0ULL;

    // prologue: fetch tile 0
    {
        a_st[0] = *(const float4*)&X[(m0 + arow     ) * CD + ac4];
        a_st[1] = *(const float4*)&X[(m0 + arow + 64) * CD + ac4];
        b_st[0] = *(const float4*)&W[(brow    ) * CD + n0 + bn4];
        b_st[1] = *(const float4*)&W[(brow + 8) * CD + n0 + bn4];
        #pragma unroll
        for (int t = 0; t < 2; t++) {
            int r = arow + t * 64;
            As[ac4 + 0][r] = a_st[t].x; As[ac4 + 1][r] = a_st[t].y;
            As[ac4 + 2][r] = a_st[t].z; As[ac4 + 3][r] = a_st[t].w;
            *(float4*)&Bs[brow + t * 8][bn4] = b_st[t];
        }
    }
    __syncthreads();

    for (int kt = 0; kt < 32; kt++) {
        if (kt < 31) {
            int kb = (kt + 1) * 16;
            a_st[0] = *(const float4*)&X[(m0 + arow     ) * CD + kb + ac4];
            a_st[1] = *(const float4*)&X[(m0 + arow + 64) * CD + kb + ac4];
            b_st[0] = *(const float4*)&W[(kb + brow    ) * CD + n0 + bn4];
            b_st[1] = *(const float4*)&W[(kb + brow + 8) * CD + n0 + bn4];
        }
        #pragma unroll
        for (int kk = 0; kk < 16; kk++) {
            float4 a0 = *(const float4*)&As[kk][ty * 8];
            float4 a1 = *(const float4*)&As[kk][ty * 8 + 4];
            float4 b0 = *(const float4*)&Bs[kk][tx * 8];
            float4 b1 = *(const float4*)&Bs[kk][tx * 8 + 4];
            ull bp[4] = { pack2(b0.x, b0.y), pack2(b0.z, b0.w),
                          pack2(b1.x, b1.y), pack2(b1.z, b1.w) };
            float av[8] = {a0.x,a0.y,a0.z,a0.w,a1.x,a1.y,a1.z,a1.w};
            #pragma unroll
            for (int i = 0; i < 8; i++) {
                ull ad = pack2(av[i], av[i]);
                #pragma unroll
                for (int j = 0; j < 4; j++) acc[i][j] = fma2(ad, bp[j], acc[i][j]);
            }
        }
        if (kt < 31) {
            __syncthreads();
            #pragma unroll
            for (int t = 0; t < 2; t++) {
                int r = arow + t * 64;
                As[ac4 + 0][r] = a_st[t].x; As[ac4 + 1][r] = a_st[t].y;
                As[ac4 + 2][r] = a_st[t].z; As[ac4 + 3][r] = a_st[t].w;
                *(float4*)&Bs[brow + t * 8][bn4] = b_st[t];
            }
            __syncthreads();
        }
    }

    // epilogue: bias + scatter
    const int nb = n0 + tx * 8;
    float bb[8];
    #pragma unroll
    for (int j = 0; j < 8; j++) bb[j] = bs[nb + j];
    const int h = nb >> 6;
    const int d = nb & 63;

    #pragma unroll
    for (int i = 0; i < 8; i++) {
        int m = m0 + ty * 8 + i;
        int bi = m >> 10, tok = m & 1023;
        float v[8];
        #pragma unroll
        for (int j = 0; j < 4; j++) {
            float2 t = unpack2(acc[i][j]);
            v[2*j] = t.x + bb[2*j]; v[2*j+1] = t.y + bb[2*j+1];
        }
        int idx;
        if (z == 0) {
            idx = ((bi * NH + h) * SEQ + tok) * HD + d;
        } else {
            int r = tok >> 5, c = tok & 31;
            int p  = ((r >> 2) << 3) + (c >> 2);
            int jj = ((r & 3) << 2) + (c & 3);
            idx = (((bi * NH + h) * PS + p) * S2 + jj) * HD + d;
        }
        *(float4*)&out[idx]     = make_float4(v[0], v[1], v[2], v[3]);
        *(float4*)&out[idx + 4] = make_float4(v[4], v[5], v[6], v[7]);
    }
}

// ---------------------------------------------------------------------------
// Attention: block = (query-chunk of 128, bh). Loops all 64 patches with
// double-buffered K/V in smem. Phase 1: thread-per-query logits+softmax
// (q in regs as f32x2 pairs, K broadcast). Phase 2: warp-per-32-queries AV,
// lane = d-pair -> dense coalesced 256B output stores.
// ---------------------------------------------------------------------------
__global__ void __launch_bounds__(128) attn_kernel(float* __restrict__ out)
{
    const int bh  = blockIdx.y;          // 0..31
    const int qc  = blockIdx.x;          // 0..7
    const int tid = threadIdx.x;
    const int warp = tid >> 5, lane = tid & 31;
    const int qi = qc * 128 + tid;

    __shared__ __align__(16) float ks[2][S2 * HD];
    __shared__ __align__(16) float vs[2][S2 * HD];
    __shared__ __align__(16) float ws[128][36];   // per query: 16 dup pairs + pad

    // q row into registers as f32x2 pairs (persistent across all 64 patches)
    ull qp[32];
    {
        const ull* q8 = (const ull*)(g_q + (bh * SEQ + qi) * HD);
        #pragma unroll
        for (int i = 0; i < 32; i++) qp[i] = q8[i];
    }

    float4 kst[2], vst[2];
    // stage patch 0
    {
        const float4* kp = (const float4*)(g_k + (bh * PS) * (S2 * HD));
        const float4* vp = (const float4*)(g_v + (bh * PS) * (S2 * HD));
        kst[0] = kp[tid]; kst[1] = kp[tid + 128];
        vst[0] = vp[tid]; vst[1] = vp[tid + 128];
        ((float4*)ks[0])[tid] = kst[0]; ((float4*)ks[0])[tid + 128] = kst[1];
        ((float4*)vs[0])[tid] = vst[0]; ((float4*)vs[0])[tid + 128] = vst[1];
    }
    __syncthreads();

    for (int p = 0; p < PS; p++) {
        const int cur = p & 1;
        if (p + 1 < PS) {
            const float4* kp = (const float4*)(g_k + (bh * PS + p + 1) * (S2 * HD));
            const float4* vp = (const float4*)(g_v + (bh * PS + p + 1) * (S2 * HD));
            kst[0] = kp[tid]; kst[1] = kp[tid + 128];
            vst[0] = vp[tid]; vst[1] = vp[tid + 128];
        }

        // ---- phase 1: logits + softmax for query `tid` ----
        {
            const float4* kb4 = (const float4*)ks[cur];
            float lg[16];
            #pragma unroll
            for (int j = 0; j < 16; j++) {
                ull a0 = 0ULL, a1 = 0ULL;
                #pragma unroll
                for (int dq = 0; dq < 16; dq++) {
                    float4 kv = kb4[j * 16 + dq];
                    a0 = fma2(qp[2*dq],   pack2(kv.x, kv.y), a0);
                    a1 = fma2(qp[2*dq+1], pack2(kv.z, kv.w), a1);
                }
                float2 t = unpack2(a0), u = unpack2(a1);
                lg[j] = (t.x + u.x) + (t.y + u.y);
            }
            float mx = lg[0];
            #pragma unroll
            for (int j = 1; j < 16; j++) mx = fmaxf(mx, lg[j]);
            float w[16], s = 0.f;
            #pragma unroll
            for (int j = 0; j < 16; j++) { w[j] = __expf((lg[j] - mx) * SCALE); s += w[j]; }
            float inv = __fdividef(1.f, s);
            #pragma unroll
            for (int j = 0; j < 8; j++) {
                float w0 = w[2*j] * inv, w1 = w[2*j+1] * inv;
                *(float4*)&ws[tid][4*j] = make_float4(w0, w0, w1, w1);
            }
        }
        __syncthreads();

        // ---- phase 2: AV. warp handles queries warp*32..+31, lane = d-pair ----
        {
            const ull* vb = (const ull*)vs[cur];
            ull vp_[16];
            #pragma unroll
            for (int j = 0; j < 16; j++) vp_[j] = vb[j * 32 + lane];
            float* ob = out + ((bh * PS + p) * SEQ + qc * 128 + warp * 32) * HD;
            for (int q = 0; q < 32; q++) {
                const float4* wq4 = (const float4*)ws[warp * 32 + q];
                ull o0 = 0ULL, o1 = 0ULL;
                #pragma unroll
                for (int jj = 0; jj < 8; jj++) {
                    float4 wv = wq4[jj];
                    o0 = fma2(pack2(wv.x, wv.y), vp_[2*jj],   o0);
                    o1 = fma2(pack2(wv.z, wv.w), vp_[2*jj+1], o1);
                }
                float2 t = unpack2(add2(o0, o1));
                *(float2*)&ob[q * HD + lane * 2] = t;
            }
        }
        __syncthreads();

        if (p + 1 < PS) {
            const int nxt = (p + 1) & 1;
            ((float4*)ks[nxt])[tid] = kst[0]; ((float4*)ks[nxt])[tid + 128] = kst[1];
            ((float4*)vs[nxt])[tid] = vst[0]; ((float4*)vs[nxt])[tid + 128] = vst[1];
            __syncthreads();
        }
    }
}

extern "C" void kernel_launch(void* const* d_in, const int* in_sizes, int n_in,
                              void* d_out, int out_size)
{
    const float* x_s = (const float*)d_in[0];
    const float* x_l = (const float*)d_in[1];
    const float* Wq  = (const float*)d_in[2];
    const float* bq  = (const float*)d_in[3];
    const float* Wk  = (const float*)d_in[4];
    const float* bk  = (const float*)d_in[5];
    const float* Wv  = (const float*)d_in[6];
    const float* bv  = (const float*)d_in[7];
    float* out = (float*)d_out;

    proj_kernel<<<dim3(4, 32, 3), 256>>>(x_s, x_l, Wq, bq, Wk, bk, Wv, bv);
    attn_kernel<<<dim3(8, 32), 128>>>(out);
}

// round 2
// speedup vs baseline: 1.0014x; 1.0014x over previous
#include <cuda_runtime.h>
#include <cstdint>

// CrossAttention: B=4, H=W=32 (N=1024), C=512, heads=8, hd=64
// q patch = whole image (1024 queries), k/v patches = 4x4 (64 patches x 16 keys)
// out[b,h,p,i,d] : [4,8,64,1024,64] fp32

typedef unsigned long long ull;

#define B_    4
#define NH    8
#define SEQ   1024
#define HD    64
#define CD    512
#define PS    64
#define S2    16
#define SCALE 0.125f

__device__ __align__(16) float g_q[B_*NH*SEQ*HD];      // [b,h,i,d]
__device__ __align__(16) float g_k[B_*NH*PS*S2*HD];    // [b,h,p,j,d]
__device__ __align__(16) float g_v[B_*NH*PS*S2*HD];

__device__ __forceinline__ ull fma2(ull a, ull b, ull c) {
    ull d; asm("fma.rn.f32x2 %0, %1, %2, %3;" : "=l"(d) : "l"(a), "l"(b), "l"(c)); return d;
}
__device__ __forceinline__ ull add2(ull a, ull b) {
    ull d; asm("add.rn.f32x2 %0, %1, %2;" : "=l"(d) : "l"(a), "l"(b)); return d;
}
__device__ __forceinline__ ull pack2(float lo, float hi) {
    ull d; asm("mov.b64 %0, {%1, %2};" : "=l"(d) : "f"(lo), "f"(hi)); return d;
}
__device__ __forceinline__ float2 unpack2(ull v) {
    float2 r; asm("mov.b64 {%0, %1}, %2;" : "=f"(r.x), "=f"(r.y) : "l"(v)); return r;
}

// ---------------------------------------------------------------------------
// Fused QKV projection: y = X @ W + b, M=4096, N=512, K=512, z picks q/k/v.
// 128x128 tile, BK=16, 256 threads, 8x8 per thread, f32x2 inner product.
// Epilogue scatters K/V into patch-grouped layout.
// ---------------------------------------------------------------------------
__global__ void __launch_bounds__(256) proj_kernel(
    const float* __restrict__ x_s, const float* __restrict__ x_l,
    const float* __restrict__ Wq, const float* __restrict__ bq,
    const float* __restrict__ Wk, const float* __restrict__ bk,
    const float* __restrict__ Wv, const float* __restrict__ bv)
{
    const int z = blockIdx.z;
    const float* X  = (z == 0) ? x_l : x_s;
    const float* W  = (z == 0) ? Wq : (z == 1 ? Wk : Wv);
    const float* bs = (z == 0) ? bq : (z == 1 ? bk : bv);
    float* out      = (z == 0) ? g_q : (z == 1 ? g_k : g_v);

    __shared__ __align__(16) float As[16][132];   // [k][m] transposed
    __shared__ __align__(16) float Bs[16][132];   // [k][n]

    const int tid = threadIdx.x;
    const int tx = tid & 15, ty = tid >> 4;
    const int m0 = blockIdx.y * 128;
    const int n0 = blockIdx.x * 128;

    const int arow = tid >> 2, ac4 = (tid & 3) * 4;
    const int brow = tid >> 5, bn4 = (tid & 31) * 4;

    float4 a_st[2], b_st[2];

    ull acc[8][4];
    #pragma unroll
    for (int i = 0; i < 8; i++)
        #pragma unroll
        for (int j = 0; j < 4; j++) acc[i][j] = 0ULL;

    // prologue: fetch tile 0
    {
        a_st[0] = *(const float4*)&X[(m0 + arow     ) * CD + ac4];
        a_st[1] = *(const float4*)&X[(m0 + arow + 64) * CD + ac4];
        b_st[0] = *(const float4*)&W[(brow    ) * CD + n0 + bn4];
        b_st[1] = *(const float4*)&W[(brow + 8) * CD + n0 + bn4];
        #pragma unroll
        for (int t = 0; t < 2; t++) {
            int r = arow + t * 64;
            As[ac4 + 0][r] = a_st[t].x; As[ac4 + 1][r] = a_st[t].y;
            As[ac4 + 2][r] = a_st[t].z; As[ac4 + 3][r] = a_st[t].w;
            *(float4*)&Bs[brow + t * 8][bn4] = b_st[t];
        }
    }
    __syncthreads();

    for (int kt = 0; kt < 32; kt++) {
        if (kt < 31) {
            int kb = (kt + 1) * 16;
            a_st[0] = *(const float4*)&X[(m0 + arow     ) * CD + kb + ac4];
            a_st[1] = *(const float4*)&X[(m0 + arow + 64) * CD + kb + ac4];
            b_st[0] = *(const float4*)&W[(kb + brow    ) * CD + n0 + bn4];
            b_st[1] = *(const float4*)&W[(kb + brow + 8) * CD + n0 + bn4];
        }
        #pragma unroll
        for (int kk = 0; kk < 16; kk++) {
            float4 a0 = *(const float4*)&As[kk][ty * 8];
            float4 a1 = *(const float4*)&As[kk][ty * 8 + 4];
            float4 b0 = *(const float4*)&Bs[kk][tx * 8];
            float4 b1 = *(const float4*)&Bs[kk][tx * 8 + 4];
            ull bp[4] = { pack2(b0.x, b0.y), pack2(b0.z, b0.w),
                          pack2(b1.x, b1.y), pack2(b1.z, b1.w) };
            float av[8] = {a0.x,a0.y,a0.z,a0.w,a1.x,a1.y,a1.z,a1.w};
            #pragma unroll
            for (int i = 0; i < 8; i++) {
                ull ad = pack2(av[i], av[i]);
                #pragma unroll
                for (int j = 0; j < 4; j++) acc[i][j] = fma2(ad, bp[j], acc[i][j]);
            }
        }
        if (kt < 31) {
            __syncthreads();
            #pragma unroll
            for (int t = 0; t < 2; t++) {
                int r = arow + t * 64;
                As[ac4 + 0][r] = a_st[t].x; As[ac4 + 1][r] = a_st[t].y;
                As[ac4 + 2][r] = a_st[t].z; As[ac4 + 3][r] = a_st[t].w;
                *(float4*)&Bs[brow + t * 8][bn4] = b_st[t];
            }
            __syncthreads();
        }
    }

    // epilogue: bias + scatter
    const int nb = n0 + tx * 8;
    float bb[8];
    #pragma unroll
    for (int j = 0; j < 8; j++) bb[j] = bs[nb + j];
    const int h = nb >> 6;
    const int d = nb & 63;

    #pragma unroll
    for (int i = 0; i < 8; i++) {
        int m = m0 + ty * 8 + i;
        int bi = m >> 10, tok = m & 1023;
        float v[8];
        #pragma unroll
        for (int j = 0; j < 4; j++) {
            float2 t = unpack2(acc[i][j]);
            v[2*j] = t.x + bb[2*j]; v[2*j+1] = t.y + bb[2*j+1];
        }
        int idx;
        if (z == 0) {
            idx = ((bi * NH + h) * SEQ + tok) * HD + d;
        } else {
            int r = tok >> 5, c = tok & 31;
            int p  = ((r >> 2) << 3) + (c >> 2);
            int jj = ((r & 3) << 2) + (c & 3);
            idx = (((bi * NH + h) * PS + p) * S2 + jj) * HD + d;
        }
        *(float4*)&out[idx]     = make_float4(v[0], v[1], v[2], v[3]);
        *(float4*)&out[idx + 4] = make_float4(v[4], v[5], v[6], v[7]);
    }
}

// ---------------------------------------------------------------------------
// Attention: block = (query-chunk of 128, bh). Loops all 64 patches with
// double-buffered K/V in smem. Phase 1: thread-per-query logits+softmax
// (q in regs as f32x2 pairs, K broadcast). Phase 2: warp-per-32-queries AV,
// lane = d-pair -> dense coalesced 256B output stores.
// ---------------------------------------------------------------------------
__global__ void __launch_bounds__(128) attn_kernel(float* __restrict__ out)
{
    const int bh  = blockIdx.y;          // 0..31
    const int qc  = blockIdx.x;          // 0..7
    const int tid = threadIdx.x;
    const int warp = tid >> 5, lane = tid & 31;
    const int qi = qc * 128 + tid;

    __shared__ __align__(16) float ks[2][S2 * HD];
    __shared__ __align__(16) float vs[2][S2 * HD];
    __shared__ __align__(16) float ws[128][36];   // per query: 16 dup pairs + pad

    // q row into registers as f32x2 pairs (persistent across all 64 patches)
    ull qp[32];
    {
        const ull* q8 = (const ull*)(g_q + (bh * SEQ + qi) * HD);
        #pragma unroll
        for (int i = 0; i < 32; i++) qp[i] = q8[i];
    }

    float4 kst[2], vst[2];
    // stage patch 0
    {
        const float4* kp = (const float4*)(g_k + (bh * PS) * (S2 * HD));
        const float4* vp = (const float4*)(g_v + (bh * PS) * (S2 * HD));
        kst[0] = kp[tid]; kst[1] = kp[tid + 128];
        vst[0] = vp[tid]; vst[1] = vp[tid + 128];
        ((float4*)ks[0])[tid] = kst[0]; ((float4*)ks[0])[tid + 128] = kst[1];
        ((float4*)vs[0])[tid] = vst[0]; ((float4*)vs[0])[tid + 128] = vst[1];
    }
    __syncthreads();

    for (int p = 0; p < PS; p++) {
        const int cur = p & 1;
        if (p + 1 < PS) {
            const float4* kp = (const float4*)(g_k + (bh * PS + p + 1) * (S2 * HD));
            const float4* vp = (const float4*)(g_v + (bh * PS + p + 1) * (S2 * HD));
            kst[0] = kp[tid]; kst[1] = kp[tid + 128];
            vst[0] = vp[tid]; vst[1] = vp[tid + 128];
        }

        // ---- phase 1: logits + softmax for query `tid` ----
        {
            const float4* kb4 = (const float4*)ks[cur];
            float lg[16];
            #pragma unroll
            for (int j = 0; j < 16; j++) {
                ull a0 = 0ULL, a1 = 0ULL;
                #pragma unroll
                for (int dq = 0; dq < 16; dq++) {
                    float4 kv = kb4[j * 16 + dq];
                    a0 = fma2(qp[2*dq],   pack2(kv.x, kv.y), a0);
                    a1 = fma2(qp[2*dq+1], pack2(kv.z, kv.w), a1);
                }
                float2 t = unpack2(a0), u = unpack2(a1);
                lg[j] = (t.x + u.x) + (t.y + u.y);
            }
            float mx = lg[0];
            #pragma unroll
            for (int j = 1; j < 16; j++) mx = fmaxf(mx, lg[j]);
            float w[16], s = 0.f;
            #pragma unroll
            for (int j = 0; j < 16; j++) { w[j] = __expf((lg[j] - mx) * SCALE); s += w[j]; }
            float inv = __fdividef(1.f, s);
            #pragma unroll
            for (int j = 0; j < 8; j++) {
                float w0 = w[2*j] * inv, w1 = w[2*j+1] * inv;
                *(float4*)&ws[tid][4*j] = make_float4(w0, w0, w1, w1);
            }
        }
        __syncthreads();

        // ---- phase 2: AV. warp handles queries warp*32..+31, lane = d-pair ----
        {
            const ull* vb = (const ull*)vs[cur];
            ull vp_[16];
            #pragma unroll
            for (int j = 0; j < 16; j++) vp_[j] = vb[j * 32 + lane];
            float* ob = out + ((bh * PS + p) * SEQ + qc * 128 + warp * 32) * HD;
            for (int q = 0; q < 32; q++) {
                const float4* wq4 = (const float4*)ws[warp * 32 + q];
                ull o0 = 0ULL, o1 = 0ULL;
                #pragma unroll
                for (int jj = 0; jj < 8; jj++) {
                    float4 wv = wq4[jj];
                    o0 = fma2(pack2(wv.x, wv.y), vp_[2*jj],   o0);
                    o1 = fma2(pack2(wv.z, wv.w), vp_[2*jj+1], o1);
                }
                float2 t = unpack2(add2(o0, o1));
                *(float2*)&ob[q * HD + lane * 2] = t;
            }
        }
        __syncthreads();

        if (p + 1 < PS) {
            const int nxt = (p + 1) & 1;
            ((float4*)ks[nxt])[tid] = kst[0]; ((float4*)ks[nxt])[tid + 128] = kst[1];
            ((float4*)vs[nxt])[tid] = vst[0]; ((float4*)vs[nxt])[tid + 128] = vst[1];
            __syncthreads();
        }
    }
}

extern "C" void kernel_launch(void* const* d_in, const int* in_sizes, int n_in,
                              void* d_out, int out_size)
{
    const float* x_s = (const float*)d_in[0];
    const float* x_l = (const float*)d_in[1];
    const float* Wq  = (const float*)d_in[2];
    const float* bq  = (const float*)d_in[3];
    const float* Wk  = (const float*)d_in[4];
    const float* bk  = (const float*)d_in[5];
    const float* Wv  = (const float*)d_in[6];
    const float* bv  = (const float*)d_in[7];
    float* out = (float*)d_out;

    proj_kernel<<<dim3(4, 32, 3), 256>>>(x_s, x_l, Wq, bq, Wk, bk, Wv, bv);
    attn_kernel<<<dim3(8, 32), 128>>>(out);
}

// round 5
// speedup vs baseline: 1.3692x; 1.3673x over previous
#include <cuda_runtime.h>
#include <cuda_bf16.h>
#include <cstdint>

typedef unsigned long long ull;
typedef uint32_t u32;

#define B_    4
#define NH    8
#define SEQ   1024
#define HD    64
#define CD    512
#define PS    64
#define S2    16

__device__ __align__(16) float g_q[B_*NH*SEQ*HD];     // [bh][i][d]  tf32-rounded
__device__ __align__(16) float g_k[B_*NH*PS*S2*HD];   // [bh][p][j][d] tf32-rounded
__device__ __align__(16) float g_v[B_*NH*PS*S2*HD];   // [bh][p][j][d] fp32
__device__ __align__(16) u32   g_vh[B_*NH*PS*HD*8];   // bf16x2 [bh][p][d][jw] hi
__device__ __align__(16) u32   g_vl[B_*NH*PS*HD*8];   // lo

__device__ __forceinline__ ull fma2(ull a, ull b, ull c) {
    ull d; asm("fma.rn.f32x2 %0, %1, %2, %3;" : "=l"(d) : "l"(a), "l"(b), "l"(c)); return d;
}
__device__ __forceinline__ ull pack2(float lo, float hi) {
    ull d; asm("mov.b64 %0, {%1, %2};" : "=l"(d) : "f"(lo), "f"(hi)); return d;
}
__device__ __forceinline__ float2 unpack2(ull v) {
    float2 r; asm("mov.b64 {%0, %1}, %2;" : "=f"(r.x), "=f"(r.y) : "l"(v)); return r;
}
__device__ __forceinline__ float tf32r(float x) {
    float y; asm("cvt.rna.tf32.f32 %0, %1;" : "=f"(y) : "f"(x)); return y;
}
__device__ __forceinline__ float ex2f(float x) {
    float y; asm("ex2.approx.f32 %0, %1;" : "=f"(y) : "f"(x)); return y;
}
__device__ __forceinline__ void mma_t32(float d[4], const u32 a[4], u32 b0, u32 b1) {
    asm volatile("mma.sync.aligned.m16n8k8.row.col.f32.tf32.tf32.f32 "
        "{%0,%1,%2,%3},{%4,%5,%6,%7},{%8,%9},{%0,%1,%2,%3};"
        : "+f"(d[0]),"+f"(d[1]),"+f"(d[2]),"+f"(d[3])
        : "r"(a[0]),"r"(a[1]),"r"(a[2]),"r"(a[3]),"r"(b0),"r"(b1));
}
__device__ __forceinline__ void mma_b16(float d[4], const u32 a[4], u32 b0, u32 b1) {
    asm volatile("mma.sync.aligned.m16n8k16.row.col.f32.bf16.bf16.f32 "
        "{%0,%1,%2,%3},{%4,%5,%6,%7},{%8,%9},{%0,%1,%2,%3};"
        : "+f"(d[0]),"+f"(d[1]),"+f"(d[2]),"+f"(d[3])
        : "r"(a[0]),"r"(a[1]),"r"(a[2]),"r"(a[3]),"r"(b0),"r"(b1));
}
__device__ __forceinline__ void split2(float x0, float x1, u32& h, u32& l) {
    __nv_bfloat162 hp = __floats2bfloat162_rn(x0, x1);
    h = *reinterpret_cast<u32*>(&hp);
    __nv_bfloat162 lp = __floats2bfloat162_rn(x0 - __bfloat162float(hp.x),
                                              x1 - __bfloat162float(hp.y));
    l = *reinterpret_cast<u32*>(&lp);
}

// ---------------- projection (proven fp32 SIMT) ----------------
__global__ void __launch_bounds__(256) proj_kernel(
    const float* __restrict__ x_s, const float* __restrict__ x_l,
    const float* __restrict__ Wq, const float* __restrict__ bq,
    const float* __restrict__ Wk, const float* __restrict__ bk,
    const float* __restrict__ Wv, const float* __restrict__ bv)
{
    const int z = blockIdx.z;
    const float* X  = (z == 0) ? x_l : x_s;
    const float* W  = (z == 0) ? Wq : (z == 1 ? Wk : Wv);
    const float* bs = (z == 0) ? bq : (z == 1 ? bk : bv);
    float* out      = (z == 0) ? g_q : (z == 1 ? g_k : g_v);

    __shared__ __align__(16) float As[16][132];
    __shared__ __align__(16) float Bs[16][132];
    const int tid = threadIdx.x, tx = tid & 15, ty = tid >> 4;
    const int m0 = blockIdx.y * 128, n0 = blockIdx.x * 128;
    const int arow = tid >> 2, ac4 = (tid & 3) * 4;
    const int brow = tid >> 5, bn4 = (tid & 31) * 4;
    float4 a_st[2], b_st[2];
    ull acc[8][4];
    #pragma unroll
    for (int i = 0; i < 8; i++)
        #pragma unroll
        for (int j = 0; j < 4; j++) acc[i][j] = 0ULL;

    a_st[0] = *(const float4*)&X[(m0 + arow     ) * CD + ac4];
    a_st[1] = *(const float4*)&X[(m0 + arow + 64) * CD + ac4];
    b_st[0] = *(const float4*)&W[(brow    ) * CD + n0 + bn4];
    b_st[1] = *(const float4*)&W[(brow + 8) * CD + n0 + bn4];
    #pragma unroll
    for (int t = 0; t < 2; t++) {
        int r = arow + t * 64;
        As[ac4+0][r] = a_st[t].x; As[ac4+1][r] = a_st[t].y;
        As[ac4+2][r] = a_st[t].z; As[ac4+3][r] = a_st[t].w;
        *(float4*)&Bs[brow + t*8][bn4] = b_st[t];
    }
    __syncthreads();

    for (int kt = 0; kt < 32; kt++) {
        if (kt < 31) {
            int kb = (kt + 1) * 16;
            a_st[0] = *(const float4*)&X[(m0 + arow     ) * CD + kb + ac4];
            a_st[1] = *(const float4*)&X[(m0 + arow + 64) * CD + kb + ac4];
            b_st[0] = *(const float4*)&W[(kb + brow    ) * CD + n0 + bn4];
            b_st[1] = *(const float4*)&W[(kb + brow + 8) * CD + n0 + bn4];
        }
        #pragma unroll
        for (int kk = 0; kk < 16; kk++) {
            float4 a0 = *(const float4*)&As[kk][ty*8];
            float4 a1 = *(const float4*)&As[kk][ty*8+4];
            float4 b0 = *(const float4*)&Bs[kk][tx*8];
            float4 b1 = *(const float4*)&Bs[kk][tx*8+4];
            ull bp[4] = { pack2(b0.x,b0.y), pack2(b0.z,b0.w),
                          pack2(b1.x,b1.y), pack2(b1.z,b1.w) };
            float av[8] = {a0.x,a0.y,a0.z,a0.w,a1.x,a1.y,a1.z,a1.w};
            #pragma unroll
            for (int i = 0; i < 8; i++) {
                ull ad = pack2(av[i], av[i]);
                #pragma unroll
                for (int j = 0; j < 4; j++) acc[i][j] = fma2(ad, bp[j], acc[i][j]);
            }
        }
        if (kt < 31) {
            __syncthreads();
            #pragma unroll
            for (int t = 0; t < 2; t++) {
                int r = arow + t * 64;
                As[ac4+0][r] = a_st[t].x; As[ac4+1][r] = a_st[t].y;
                As[ac4+2][r] = a_st[t].z; As[ac4+3][r] = a_st[t].w;
                *(float4*)&Bs[brow + t*8][bn4] = b_st[t];
            }
            __syncthreads();
        }
    }

    const int nb = n0 + tx * 8;
    float bb[8];
    #pragma unroll
    for (int j = 0; j < 8; j++) bb[j] = bs[nb + j];
    const int h = nb >> 6, d = nb & 63;
    #pragma unroll
    for (int i = 0; i < 8; i++) {
        int m = m0 + ty * 8 + i;
        int bi = m >> 10, tok = m & 1023;
        float v[8];
        #pragma unroll
        for (int j = 0; j < 4; j++) {
            float2 t = unpack2(acc[i][j]);
            v[2*j] = t.x + bb[2*j]; v[2*j+1] = t.y + bb[2*j+1];
        }
        if (z <= 1) {
            #pragma unroll
            for (int e = 0; e < 8; e++) v[e] = tf32r(v[e]);
        }
        int idx;
        if (z == 0) idx = ((bi * NH + h) * SEQ + tok) * HD + d;
        else {
            int r = tok >> 5, c = tok & 31;
            int p  = ((r >> 2) << 3) + (c >> 2);
            int jj = ((r & 3) << 2) + (c & 3);
            idx = (((bi * NH + h) * PS + p) * S2 + jj) * HD + d;
        }
        *(float4*)&out[idx]     = make_float4(v[0], v[1], v[2], v[3]);
        *(float4*)&out[idx + 4] = make_float4(v[4], v[5], v[6], v[7]);
    }
}

// ---------------- V transpose + bf16 hi/lo split ----------------
__global__ void __launch_bounds__(64) vprep_kernel()
{
    __shared__ float vs[S2 * HD];
    const int bh = blockIdx.y, p = blockIdx.x, tid = threadIdx.x;
    const float4* src = (const float4*)(g_v + (bh * PS + p) * (S2 * HD));
    #pragma unroll
    for (int i = 0; i < 4; i++) {
        int f = tid + i * 64;
        ((float4*)vs)[f] = src[f];
    }
    __syncthreads();
    float v[16];
    #pragma unroll
    for (int j = 0; j < 16; j++) v[j] = vs[j * HD + tid];
    u32 hw[8], lw[8];
    #pragma unroll
    for (int w = 0; w < 8; w++) split2(v[2*w], v[2*w+1], hw[w], lw[w]);
    u32 base = ((bh * PS + p) * HD + tid) * 8;
    *(uint4*)&g_vh[base]     = make_uint4(hw[0], hw[1], hw[2], hw[3]);
    *(uint4*)&g_vh[base + 4] = make_uint4(hw[4], hw[5], hw[6], hw[7]);
    *(uint4*)&g_vl[base]     = make_uint4(lw[0], lw[1], lw[2], lw[3]);
    *(uint4*)&g_vl[base + 4] = make_uint4(lw[4], lw[5], lw[6], lw[7]);
}

// ---------------- mma.sync attention ----------------
// smem (floats): Q [128][68] @0 (8704) | K 2x[64][68] @8704 | stage 8x[16][68] @17408
#define QS_OFF 0
#define KS_OFF 8704
#define ST_OFF 17408
#define SMEM_FLOATS 26112

__global__ void __launch_bounds__(256, 2) attn_mma_kernel(float* __restrict__ out)
{
    extern __shared__ float sm[];
    const int tid = threadIdx.x, warp = tid >> 5, lane = tid & 31;
    const int g = lane >> 2, tig = lane & 3;
    const int bh = blockIdx.y, qt = blockIdx.x;
    const int wq = warp * 16;
    const float C_EXP = 0.125f * 1.44269504f;

    // load Q tile [128][64] -> [128][68]
    {
        const float4* qs = (const float4*)(g_q + (bh * SEQ + qt * 128) * HD);
        #pragma unroll
        for (int i = 0; i < 8; i++) {
            int f = tid + i * 256;
            float4 x = qs[f];
            *(float4*)&sm[QS_OFF + (f >> 4) * 68 + (f & 15) * 4] = x;
        }
    }
    // load K chunk 0
    {
        const float4* ks = (const float4*)(g_k + (bh * PS) * (S2 * HD));
        #pragma unroll
        for (int i = 0; i < 4; i++) {
            int f = tid + i * 256;
            float4 x = ks[f];
            *(float4*)&sm[KS_OFF + (f >> 4) * 68 + (f & 15) * 4] = x;
        }
    }
    __syncthreads();

    float* stw = sm + ST_OFF + warp * 1088;
    const int r2 = lane >> 4, d4 = (lane & 15) * 4;

    for (int c = 0; c < 16; c++) {
        const int buf = c & 1;
        const float* kb = sm + KS_OFF + buf * 4352;

        // ---- S = Q K^T : tf32 m16n8k8 ----
        u32 qa[8][4];
        #pragma unroll
        for (int ks = 0; ks < 8; ks++) {
            qa[ks][0] = __float_as_uint(sm[QS_OFF + (wq + g    ) * 68 + ks*8 + tig]);
            qa[ks][1] = __float_as_uint(sm[QS_OFF + (wq + g + 8) * 68 + ks*8 + tig]);
            qa[ks][2] = __float_as_uint(sm[QS_OFF + (wq + g    ) * 68 + ks*8 + tig + 4]);
            qa[ks][3] = __float_as_uint(sm[QS_OFF + (wq + g + 8) * 68 + ks*8 + tig + 4]);
        }
        float DS[8][4];
        #pragma unroll
        for (int n = 0; n < 8; n++) {
            DS[n][0]=DS[n][1]=DS[n][2]=DS[n][3]=0.f;
            #pragma unroll
            for (int ks = 0; ks < 8; ks++) {
                u32 b0 = __float_as_uint(kb[(8*n + g) * 68 + ks*8 + tig]);
                u32 b1 = __float_as_uint(kb[(8*n + g) * 68 + ks*8 + tig + 4]);
                mma_t32(DS[n], qa[ks], b0, b1);
            }
        }

        // ---- softmax per 16-key group (2 n-tiles) ----
        #pragma unroll
        for (int G = 0; G < 4; G++) {
            float* t0 = DS[2*G]; float* t1 = DS[2*G+1];
            float m0 = fmaxf(fmaxf(t0[0], t0[1]), fmaxf(t1[0], t1[1]));
            float m1 = fmaxf(fmaxf(t0[2], t0[3]), fmaxf(t1[2], t1[3]));
            m0 = fmaxf(m0, __shfl_xor_sync(~0u, m0, 1));
            m0 = fmaxf(m0, __shfl_xor_sync(~0u, m0, 2));
            m1 = fmaxf(m1, __shfl_xor_sync(~0u, m1, 1));
            m1 = fmaxf(m1, __shfl_xor_sync(~0u, m1, 2));
            t0[0] = ex2f((t0[0]-m0)*C_EXP); t0[1] = ex2f((t0[1]-m0)*C_EXP);
            t1[0] = ex2f((t1[0]-m0)*C_EXP); t1[1] = ex2f((t1[1]-m0)*C_EXP);
            t0[2] = ex2f((t0[2]-m1)*C_EXP); t0[3] = ex2f((t0[3]-m1)*C_EXP);
            t1[2] = ex2f((t1[2]-m1)*C_EXP); t1[3] = ex2f((t1[3]-m1)*C_EXP);
            float s0 = t0[0]+t0[1]+t1[0]+t1[1];
            float s1 = t0[2]+t0[3]+t1[2]+t1[3];
            s0 += __shfl_xor_sync(~0u, s0, 1); s0 += __shfl_xor_sync(~0u, s0, 2);
            s1 += __shfl_xor_sync(~0u, s1, 1); s1 += __shfl_xor_sync(~0u, s1, 2);
            float r0 = __frcp_rn(s0), r1 = __frcp_rn(s1);
            t0[0]*=r0; t0[1]*=r0; t1[0]*=r0; t1[1]*=r0;
            t0[2]*=r1; t0[3]*=r1; t1[2]*=r1; t1[3]*=r1;
        }

        // ---- per patch: O = P V (bf16 3-term), stage, store ----
        #pragma unroll
        for (int p = 0; p < 4; p++) {
            float* t0 = DS[2*p]; float* t1 = DS[2*p+1];
            u32 ah[4], al[4];
            split2(t0[0], t0[1], ah[0], al[0]);
            split2(t0[2], t0[3], ah[1], al[1]);
            split2(t1[0], t1[1], ah[2], al[2]);
            split2(t1[2], t1[3], ah[3], al[3]);

            const u32* vh = g_vh + ((bh * PS + c*4 + p) * HD) * 8;
            const u32* vl = g_vl + ((bh * PS + c*4 + p) * HD) * 8;
            float DO[8][4];
            #pragma unroll
            for (int n = 0; n < 8; n++) {
                DO[n][0]=DO[n][1]=DO[n][2]=DO[n][3]=0.f;
                int w0 = (8*n + g) * 8 + tig;
                u32 bh0 = vh[w0], bh1 = vh[w0 + 4];
                u32 bl0 = vl[w0], bl1 = vl[w0 + 4];
                mma_b16(DO[n], ah, bh0, bh1);
                mma_b16(DO[n], ah, bl0, bl1);
                mma_b16(DO[n], al, bh0, bh1);
            }
            __syncwarp();
            #pragma unroll
            for (int n = 0; n < 8; n++) {
                *(float2*)&stw[ g      * 68 + 8*n + 2*tig] = make_float2(DO[n][0], DO[n][1]);
                *(float2*)&stw[(g + 8) * 68 + 8*n + 2*tig] = make_float2(DO[n][2], DO[n][3]);
            }
            __syncwarp();
            float* ob = out + (((size_t)(bh * PS + c*4 + p) * SEQ) + qt*128 + wq) * HD;
            #pragma unroll
            for (int i = 0; i < 8; i++) {
                int row = 2*i + r2;
                float4 f = *(float4*)&stw[row * 68 + d4];
                *(float4*)&ob[row * 64 + d4] = f;
            }
            __syncwarp();
        }

        // ---- prefetch next K chunk ----
        __syncthreads();
        if (c < 15) {
            const float4* ks = (const float4*)(g_k + (bh * PS + (c+1)*4) * (S2 * HD));
            float* kn = sm + KS_OFF + (buf ^ 1) * 4352;
            #pragma unroll
            for (int i = 0; i < 4; i++) {
                int f = tid + i * 256;
                float4 x = ks[f];
                *(float4*)&kn[(f >> 4) * 68 + (f & 15) * 4] = x;
            }
        }
        __syncthreads();
    }
}

extern "C" void kernel_launch(void* const* d_in, const int* in_sizes, int n_in,
                              void* d_out, int out_size)
{
    const float* x_s = (const float*)d_in[0];
    const float* x_l = (const float*)d_in[1];
    const float* Wq  = (const float*)d_in[2];
    const float* bq  = (const float*)d_in[3];
    const float* Wk  = (const float*)d_in[4];
    const float* bk  = (const float*)d_in[5];
    const float* Wv  = (const float*)d_in[6];
    const float* bv  = (const float*)d_in[7];
    float* out = (float*)d_out;

    cudaFuncSetAttribute(attn_mma_kernel, cudaFuncAttributeMaxDynamicSharedMemorySize,
                         SMEM_FLOATS * 4);

    proj_kernel<<<dim3(4, 32, 3), 256>>>(x_s, x_l, Wq, bq, Wk, bk, Wv, bv);
    vprep_kernel<<<dim3(PS, 32), 64>>>();
    attn_mma_kernel<<<dim3(8, 32), 256, SMEM_FLOATS * 4>>>(out);
}

// round 6
// speedup vs baseline: 1.6644x; 1.2156x over previous
#include <cuda_runtime.h>
#include <cuda_bf16.h>
#include <cstdint>

typedef unsigned long long ull;
typedef uint32_t u32;

#define B_    4
#define NH    8
#define SEQ   1024
#define HD    64
#define CD    512
#define PS    64
#define S2    16

__device__ __align__(16) float g_q[B_*NH*SEQ*HD];     // [bh][i][d]  tf32-rounded
__device__ __align__(16) float g_k[B_*NH*PS*S2*HD];   // [bh][p][j][d] tf32-rounded
__device__ __align__(16) float g_v[B_*NH*PS*S2*HD];   // [bh][p][j][d] fp32
__device__ __align__(16) u32   g_vh[B_*NH*PS*HD*8];   // bf16x2 [bh][p][d][jw] hi
__device__ __align__(16) u32   g_vl[B_*NH*PS*HD*8];   // lo
// pre-split GEMM operands (bf16 hi/lo, packed u32 = 2 consecutive k)
__device__ __align__(16) u32 g_xh[2*4096*256];        // [src][m][k/2]
__device__ __align__(16) u32 g_xl[2*4096*256];
__device__ __align__(16) u32 g_wh[3*512*256];         // [z][n][k/2]  (W transposed)
__device__ __align__(16) u32 g_wl[3*512*256];

__device__ __forceinline__ float tf32r(float x) {
    float y; asm("cvt.rna.tf32.f32 %0, %1;" : "=f"(y) : "f"(x)); return y;
}
__device__ __forceinline__ float ex2f(float x) {
    float y; asm("ex2.approx.f32 %0, %1;" : "=f"(y) : "f"(x)); return y;
}
__device__ __forceinline__ void mma_t32(float d[4], const u32 a[4], u32 b0, u32 b1) {
    asm volatile("mma.sync.aligned.m16n8k8.row.col.f32.tf32.tf32.f32 "
        "{%0,%1,%2,%3},{%4,%5,%6,%7},{%8,%9},{%0,%1,%2,%3};"
        : "+f"(d[0]),"+f"(d[1]),"+f"(d[2]),"+f"(d[3])
        : "r"(a[0]),"r"(a[1]),"r"(a[2]),"r"(a[3]),"r"(b0),"r"(b1));
}
__device__ __forceinline__ void mma_b16(float d[4], const u32 a[4], u32 b0, u32 b1) {
    asm volatile("mma.sync.aligned.m16n8k16.row.col.f32.bf16.bf16.f32 "
        "{%0,%1,%2,%3},{%4,%5,%6,%7},{%8,%9},{%0,%1,%2,%3};"
        : "+f"(d[0]),"+f"(d[1]),"+f"(d[2]),"+f"(d[3])
        : "r"(a[0]),"r"(a[1]),"r"(a[2]),"r"(a[3]),"r"(b0),"r"(b1));
}
__device__ __forceinline__ void split2(float x0, float x1, u32& h, u32& l) {
    __nv_bfloat162 hp = __floats2bfloat162_rn(x0, x1);
    h = *reinterpret_cast<u32*>(&hp);
    __nv_bfloat162 lp = __floats2bfloat162_rn(x0 - __bfloat162float(hp.x),
                                              x1 - __bfloat162float(hp.y));
    l = *reinterpret_cast<u32*>(&lp);
}
__device__ __forceinline__ u32 smem_u32p(const void* p) {
    u32 a;
    asm("{ .reg .u64 t; cvta.to.shared.u64 t, %1; cvt.u32.u64 %0, t; }" : "=r"(a) : "l"(p));
    return a;
}
#define CPA(dst, src) asm volatile("cp.async.cg.shared.global [%0], [%1], 16;" :: "r"(dst), "l"(src) : "memory")
#define CPC()         asm volatile("cp.async.commit_group;" ::: "memory")
#define CPW(n)        asm volatile("cp.async.wait_group %0;" :: "n"(n) : "memory")

// ---------------- prep: split X (x_l -> slot0, x_s -> slot1) ----------------
__global__ void __launch_bounds__(256) splitx_kernel(
    const float* __restrict__ x_l, const float* __restrict__ x_s)
{
    const int src = blockIdx.y;
    const float* X = src ? x_s : x_l;
    int idx = blockIdx.x * 256 + threadIdx.x;      // float4 index, 524288 total
    float4 f = ((const float4*)X)[idx];
    u32 h0, l0, h1, l1;
    split2(f.x, f.y, h0, l0);
    split2(f.z, f.w, h1, l1);
    u32 base = src * (4096 * 256) + idx * 2;
    *(uint2*)&g_xh[base] = make_uint2(h0, h1);
    *(uint2*)&g_xl[base] = make_uint2(l0, l1);
}

// ---------------- prep: transpose + split W ----------------
__global__ void __launch_bounds__(256) splitw_kernel(
    const float* __restrict__ Wq, const float* __restrict__ Wk, const float* __restrict__ Wv)
{
    const int z = blockIdx.z;
    const float* W = (z == 0) ? Wq : (z == 1 ? Wk : Wv);
    __shared__ float ws[64][65];
    const int tid = threadIdx.x;
    const int k0 = blockIdx.y * 64, n0 = blockIdx.x * 64;
    #pragma unroll
    for (int i = 0; i < 4; i++) {
        int r = (tid >> 4) + i * 16;
        float4 f = *(const float4*)&W[(k0 + r) * CD + n0 + (tid & 15) * 4];
        ws[r][(tid & 15) * 4 + 0] = f.x; ws[r][(tid & 15) * 4 + 1] = f.y;
        ws[r][(tid & 15) * 4 + 2] = f.z; ws[r][(tid & 15) * 4 + 3] = f.w;
    }
    __syncthreads();
    const int n = tid >> 2, kg = (tid & 3) * 16;
    u32 h[8], l[8];
    #pragma unroll
    for (int j = 0; j < 8; j++)
        split2(ws[kg + 2*j][n], ws[kg + 2*j + 1][n], h[j], l[j]);
    u32 base = (u32)(z * 512 + n0 + n) * 256 + (k0 + kg) / 2;
    *(uint4*)&g_wh[base]     = make_uint4(h[0], h[1], h[2], h[3]);
    *(uint4*)&g_wh[base + 4] = make_uint4(h[4], h[5], h[6], h[7]);
    *(uint4*)&g_wl[base]     = make_uint4(l[0], l[1], l[2], l[3]);
    *(uint4*)&g_wl[base + 4] = make_uint4(l[4], l[5], l[6], l[7]);
}

// ---------------- projection: bf16 3-term mma.sync ----------------
// block 128m x 128n, 8 warps (4m x 2n), warp tile 32x64. K chunks of 16.
__global__ void __launch_bounds__(256, 2) proj_mma_kernel(
    const float* __restrict__ bq, const float* __restrict__ bk, const float* __restrict__ bv)
{
    const int z = blockIdx.z;
    const u32* Xh = g_xh + (z ? 1 : 0) * (4096 * 256);
    const u32* Xl = g_xl + (z ? 1 : 0) * (4096 * 256);
    const u32* Wh = g_wh + z * (512 * 256);
    const u32* Wl = g_wl + z * (512 * 256);
    const float* bsz = (z == 0) ? bq : (z == 1 ? bk : bv);
    float* out = (z == 0) ? g_q : (z == 1 ? g_k : g_v);

    // [buf][arr: xh,xl,wh,wl][128 rows x 12 u32 (8 data + 4 pad)]
    __shared__ u32 sb[2][4][128 * 12];

    const int tid = threadIdx.x, warp = tid >> 5, lane = tid & 31;
    const int g = lane >> 2, tig = lane & 3;
    const int m0 = blockIdx.y * 128, n0 = blockIdx.x * 128;
    const int wm = (warp & 3) * 32, wn = (warp >> 2) * 64;

    float acc[2][8][4];
    #pragma unroll
    for (int mt = 0; mt < 2; mt++)
        #pragma unroll
        for (int nt = 0; nt < 8; nt++)
            #pragma unroll
            for (int e = 0; e < 4; e++) acc[mt][nt][e] = 0.f;

    const int pr = tid >> 1, pc = (tid & 1) * 4;    // cp.async: row, u32-col
    // prologue: chunk 0 -> buf 0
    {
        u32 d0 = smem_u32p(&sb[0][0][pr * 12 + pc]);
        u32 d1 = smem_u32p(&sb[0][1][pr * 12 + pc]);
        u32 d2 = smem_u32p(&sb[0][2][pr * 12 + pc]);
        u32 d3 = smem_u32p(&sb[0][3][pr * 12 + pc]);
        CPA(d0, &Xh[(m0 + pr) * 256 + pc]);
        CPA(d1, &Xl[(m0 + pr) * 256 + pc]);
        CPA(d2, &Wh[(n0 + pr) * 256 + pc]);
        CPA(d3, &Wl[(n0 + pr) * 256 + pc]);
        CPC();
    }

    for (int kt = 0; kt < 32; kt++) {
        const int buf = kt & 1;
        if (kt < 31) {
            const int nb = buf ^ 1, kc = (kt + 1) * 8;
            u32 d0 = smem_u32p(&sb[nb][0][pr * 12 + pc]);
            u32 d1 = smem_u32p(&sb[nb][1][pr * 12 + pc]);
            u32 d2 = smem_u32p(&sb[nb][2][pr * 12 + pc]);
            u32 d3 = smem_u32p(&sb[nb][3][pr * 12 + pc]);
            CPA(d0, &Xh[(m0 + pr) * 256 + kc + pc]);
            CPA(d1, &Xl[(m0 + pr) * 256 + kc + pc]);
            CPA(d2, &Wh[(n0 + pr) * 256 + kc + pc]);
            CPA(d3, &Wl[(n0 + pr) * 256 + kc + pc]);
            CPC();
            CPW(1);
        } else {
            CPW(0);
        }
        __syncthreads();

        const u32* sxh = sb[buf][0];
        const u32* sxl = sb[buf][1];
        const u32* swh = sb[buf][2];
        const u32* swl = sb[buf][3];

        u32 ah[2][4], al[2][4];
        #pragma unroll
        for (int mt = 0; mt < 2; mt++) {
            int r0 = (wm + mt * 16 + g) * 12, r1 = r0 + 8 * 12;
            ah[mt][0] = sxh[r0 + tig];     ah[mt][1] = sxh[r1 + tig];
            ah[mt][2] = sxh[r0 + tig + 4]; ah[mt][3] = sxh[r1 + tig + 4];
            al[mt][0] = sxl[r0 + tig];     al[mt][1] = sxl[r1 + tig];
            al[mt][2] = sxl[r0 + tig + 4]; al[mt][3] = sxl[r1 + tig + 4];
        }
        #pragma unroll
        for (int nt = 0; nt < 8; nt++) {
            int rb = (wn + nt * 8 + g) * 12;
            u32 bh0 = swh[rb + tig], bh1 = swh[rb + tig + 4];
            u32 bl0 = swl[rb + tig], bl1 = swl[rb + tig + 4];
            #pragma unroll
            for (int mt = 0; mt < 2; mt++) {
                mma_b16(acc[mt][nt], ah[mt], bh0, bh1);
                mma_b16(acc[mt][nt], ah[mt], bl0, bl1);
                mma_b16(acc[mt][nt], al[mt], bh0, bh1);
            }
        }
        __syncthreads();
    }

    // epilogue: bias + scatter
    #pragma unroll
    for (int mt = 0; mt < 2; mt++) {
        #pragma unroll
        for (int half = 0; half < 2; half++) {
            int m = m0 + wm + mt * 16 + g + half * 8;
            int bi = m >> 10, tok = m & 1023;
            #pragma unroll
            for (int nt = 0; nt < 8; nt++) {
                int gn = n0 + wn + nt * 8 + tig * 2;
                float2 bb = *(const float2*)&bsz[gn];
                float v0 = acc[mt][nt][half * 2 + 0] + bb.x;
                float v1 = acc[mt][nt][half * 2 + 1] + bb.y;
                if (z <= 1) { v0 = tf32r(v0); v1 = tf32r(v1); }
                int h = gn >> 6, d = gn & 63;
                int idx;
                if (z == 0) idx = ((bi * NH + h) * SEQ + tok) * HD + d;
                else {
                    int rr = tok >> 5, cc = tok & 31;
                    int p  = ((rr >> 2) << 3) + (cc >> 2);
                    int jj = ((rr & 3) << 2) + (cc & 3);
                    idx = (((bi * NH + h) * PS + p) * S2 + jj) * HD + d;
                }
                *(float2*)&out[idx] = make_float2(v0, v1);
            }
        }
    }
}

// ---------------- V transpose + bf16 hi/lo split ----------------
__global__ void __launch_bounds__(64) vprep_kernel()
{
    __shared__ float vs[S2 * HD];
    const int bh = blockIdx.y, p = blockIdx.x, tid = threadIdx.x;
    const float4* src = (const float4*)(g_v + (bh * PS + p) * (S2 * HD));
    #pragma unroll
    for (int i = 0; i < 4; i++) {
        int f = tid + i * 64;
        ((float4*)vs)[f] = src[f];
    }
    __syncthreads();
    float v[16];
    #pragma unroll
    for (int j = 0; j < 16; j++) v[j] = vs[j * HD + tid];
    u32 hw[8], lw[8];
    #pragma unroll
    for (int w = 0; w < 8; w++) split2(v[2*w], v[2*w+1], hw[w], lw[w]);
    u32 base = ((bh * PS + p) * HD + tid) * 8;
    *(uint4*)&g_vh[base]     = make_uint4(hw[0], hw[1], hw[2], hw[3]);
    *(uint4*)&g_vh[base + 4] = make_uint4(hw[4], hw[5], hw[6], hw[7]);
    *(uint4*)&g_vl[base]     = make_uint4(lw[0], lw[1], lw[2], lw[3]);
    *(uint4*)&g_vl[base + 4] = make_uint4(lw[4], lw[5], lw[6], lw[7]);
}

// ---------------- mma.sync attention (round-5, + early K prefetch) ----------------
#define QS_OFF 0
#define KS_OFF 8704
#define ST_OFF 17408
#define SMEM_FLOATS 26112

__global__ void __launch_bounds__(256, 2) attn_mma_kernel(float* __restrict__ out)
{
    extern __shared__ float sm[];
    const int tid = threadIdx.x, warp = tid >> 5, lane = tid & 31;
    const int g = lane >> 2, tig = lane & 3;
    const int bh = blockIdx.y, qt = blockIdx.x;
    const int wq = warp * 16;
    const float C_EXP = 0.125f * 1.44269504f;

    {
        const float4* qs = (const float4*)(g_q + (bh * SEQ + qt * 128) * HD);
        #pragma unroll
        for (int i = 0; i < 8; i++) {
            int f = tid + i * 256;
            float4 x = qs[f];
            *(float4*)&sm[QS_OFF + (f >> 4) * 68 + (f & 15) * 4] = x;
        }
    }
    {
        const float4* ks = (const float4*)(g_k + (bh * PS) * (S2 * HD));
        #pragma unroll
        for (int i = 0; i < 4; i++) {
            int f = tid + i * 256;
            float4 x = ks[f];
            *(float4*)&sm[KS_OFF + (f >> 4) * 68 + (f & 15) * 4] = x;
        }
    }
    __syncthreads();

    float* stw = sm + ST_OFF + warp * 1088;
    const int r2 = lane >> 4, d4 = (lane & 15) * 4;

    for (int c = 0; c < 16; c++) {
        const int buf = c & 1;
        const float* kb = sm + KS_OFF + buf * 4352;

        // early prefetch LDGs for next K chunk
        float4 kpre[4];
        if (c < 15) {
            const float4* ks = (const float4*)(g_k + (bh * PS + (c+1)*4) * (S2 * HD));
            #pragma unroll
            for (int i = 0; i < 4; i++) kpre[i] = ks[tid + i * 256];
        }

        // ---- S = Q K^T : tf32 m16n8k8 ----
        u32 qa[8][4];
        #pragma unroll
        for (int ks = 0; ks < 8; ks++) {
            qa[ks][0] = __float_as_uint(sm[QS_OFF + (wq + g    ) * 68 + ks*8 + tig]);
            qa[ks][1] = __float_as_uint(sm[QS_OFF + (wq + g + 8) * 68 + ks*8 + tig]);
            qa[ks][2] = __float_as_uint(sm[QS_OFF + (wq + g    ) * 68 + ks*8 + tig + 4]);
            qa[ks][3] = __float_as_uint(sm[QS_OFF + (wq + g + 8) * 68 + ks*8 + tig + 4]);
        }
        float DS[8][4];
        #pragma unroll
        for (int n = 0; n < 8; n++) {
            DS[n][0]=DS[n][1]=DS[n][2]=DS[n][3]=0.f;
            #pragma unroll
            for (int ks = 0; ks < 8; ks++) {
                u32 b0 = __float_as_uint(kb[(8*n + g) * 68 + ks*8 + tig]);
                u32 b1 = __float_as_uint(kb[(8*n + g) * 68 + ks*8 + tig + 4]);
                mma_t32(DS[n], qa[ks], b0, b1);
            }
        }

        // ---- softmax per 16-key group ----
        #pragma unroll
        for (int G = 0; G < 4; G++) {
            float* t0 = DS[2*G]; float* t1 = DS[2*G+1];
            float m0 = fmaxf(fmaxf(t0[0], t0[1]), fmaxf(t1[0], t1[1]));
            float m1 = fmaxf(fmaxf(t0[2], t0[3]), fmaxf(t1[2], t1[3]));
            m0 = fmaxf(m0, __shfl_xor_sync(~0u, m0, 1));
            m0 = fmaxf(m0, __shfl_xor_sync(~0u, m0, 2));
            m1 = fmaxf(m1, __shfl_xor_sync(~0u, m1, 1));
            m1 = fmaxf(m1, __shfl_xor_sync(~0u, m1, 2));
            t0[0] = ex2f((t0[0]-m0)*C_EXP); t0[1] = ex2f((t0[1]-m0)*C_EXP);
            t1[0] = ex2f((t1[0]-m0)*C_EXP); t1[1] = ex2f((t1[1]-m0)*C_EXP);
            t0[2] = ex2f((t0[2]-m1)*C_EXP); t0[3] = ex2f((t0[3]-m1)*C_EXP);
            t1[2] = ex2f((t1[2]-m1)*C_EXP); t1[3] = ex2f((t1[3]-m1)*C_EXP);
            float s0 = t0[0]+t0[1]+t1[0]+t1[1];
            float s1 = t0[2]+t0[3]+t1[2]+t1[3];
            s0 += __shfl_xor_sync(~0u, s0, 1); s0 += __shfl_xor_sync(~0u, s0, 2);
            s1 += __shfl_xor_sync(~0u, s1, 1); s1 += __shfl_xor_sync(~0u, s1, 2);
            float r0 = __frcp_rn(s0), r1 = __frcp_rn(s1);
            t0[0]*=r0; t0[1]*=r0; t1[0]*=r0; t1[1]*=r0;
            t0[2]*=r1; t0[3]*=r1; t1[2]*=r1; t1[3]*=r1;
        }

        // ---- per patch: O = P V (bf16 3-term), stage, store ----
        #pragma unroll
        for (int p = 0; p < 4; p++) {
            float* t0 = DS[2*p]; float* t1 = DS[2*p+1];
            u32 ah[4], al[4];
            split2(t0[0], t0[1], ah[0], al[0]);
            split2(t0[2], t0[3], ah[1], al[1]);
            split2(t1[0], t1[1], ah[2], al[2]);
            split2(t1[2], t1[3], ah[3], al[3]);

            const u32* vh = g_vh + ((bh * PS + c*4 + p) * HD) * 8;
            const u32* vl = g_vl + ((bh * PS + c*4 + p) * HD) * 8;
            float DO[8][4];
            #pragma unroll
            for (int n = 0; n < 8; n++) {
                DO[n][0]=DO[n][1]=DO[n][2]=DO[n][3]=0.f;
                int w0 = (8*n + g) * 8 + tig;
                u32 bh0 = vh[w0], bh1 = vh[w0 + 4];
                u32 bl0 = vl[w0], bl1 = vl[w0 + 4];
                mma_b16(DO[n], ah, bh0, bh1);
                mma_b16(DO[n], ah, bl0, bl1);
                mma_b16(DO[n], al, bh0, bh1);
            }
            __syncwarp();
            #pragma unroll
            for (int n = 0; n < 8; n++) {
                *(float2*)&stw[ g      * 68 + 8*n + 2*tig] = make_float2(DO[n][0], DO[n][1]);
                *(float2*)&stw[(g + 8) * 68 + 8*n + 2*tig] = make_float2(DO[n][2], DO[n][3]);
            }
            __syncwarp();
            float* ob = out + (((size_t)(bh * PS + c*4 + p) * SEQ) + qt*128 + wq) * HD;
            #pragma unroll
            for (int i = 0; i < 8; i++) {
                int row = 2*i + r2;
                float4 f = *(float4*)&stw[row * 68 + d4];
                *(float4*)&ob[row * 64 + d4] = f;
            }
            __syncwarp();
        }

        __syncthreads();
        if (c < 15) {
            float* kn = sm + KS_OFF + (buf ^ 1) * 4352;
            #pragma unroll
            for (int i = 0; i < 4; i++) {
                int f = tid + i * 256;
                *(float4*)&kn[(f >> 4) * 68 + (f & 15) * 4] = kpre[i];
            }
        }
        __syncthreads();
    }
}

extern "C" void kernel_launch(void* const* d_in, const int* in_sizes, int n_in,
                              void* d_out, int out_size)
{
    const float* x_s = (const float*)d_in[0];
    const float* x_l = (const float*)d_in[1];
    const float* Wq  = (const float*)d_in[2];
    const float* bq  = (const float*)d_in[3];
    const float* Wk  = (const float*)d_in[4];
    const float* bk  = (const float*)d_in[5];
    const float* Wv  = (const float*)d_in[6];
    const float* bv  = (const float*)d_in[7];
    float* out = (float*)d_out;

    cudaFuncSetAttribute(attn_mma_kernel, cudaFuncAttributeMaxDynamicSharedMemorySize,
                         SMEM_FLOATS * 4);

    splitx_kernel<<<dim3(2048, 2), 256>>>(x_l, x_s);
    splitw_kernel<<<dim3(8, 8, 3), 256>>>(Wq, Wk, Wv);
    proj_mma_kernel<<<dim3(4, 32, 3), 256>>>(bq, bk, bv);
    vprep_kernel<<<dim3(PS, 32), 64>>>();
    attn_mma_kernel<<<dim3(8, 32), 256, SMEM_FLOATS * 4>>>(out);
}